// round 1
// baseline (speedup 1.0000x reference)
#include <cuda_runtime.h>
#include <cstddef>
#include <cstdint>

// ---------------- problem constants ----------------
#define BQ     4
#define DMODEL 1024
#define LSEQ   2048
#define DINNER 2048
#define DSTATE 16
#define DTRANK 64
#define BL     8192          // BQ * LSEQ
#define XPN    96            // DTRANK + 2*DSTATE

// ---------------- scratch (device globals; no allocation allowed) ----------------
__device__ float g_xz   [(size_t)BL * 4096];        // in_proj output: u | z
__device__ float g_uc   [(size_t)BL * DINNER];      // post conv+silu u
__device__ float g_part [(size_t)8 * BL * XPN];     // split-K partials for x_proj
__device__ float g_xdbl [(size_t)BL * XPN];         // dt_low | B | C
__device__ float g_delta[(size_t)BL * DINNER];
__device__ float g_y    [(size_t)BL * DINNER];
__device__ float g_o1   [(size_t)BL * DMODEL];

__device__ __forceinline__ float softplusf(float x) {
    return (x > 20.f) ? x : log1pf(__expf(x));
}
__device__ __forceinline__ float siluf(float x) {
    return x / (1.f + __expf(-x));
}

// ---------------- generic GEMM: C[M,N] = A[M,K] @ W[N,K]^T ----------------
// ALAY 0: A row-major with leading dim lda.
// ALAY 1: A is x in (B, DMODEL, L) layout; A[m,k] = x[(b*DMODEL+k)*L + l], m=b*L+l.
// EPI  0: plain store (with blockIdx.z partial offset for split-K)
// EPI  1: softplus(acc + bias[n])
// EPI  2: acc + bias[n], stored transposed to out (B, DMODEL, L)
template<int ALAY, int EPI>
__global__ void gemm_k(const float* __restrict__ A, const float* __restrict__ W,
                       const float* __restrict__ bias, float* __restrict__ C,
                       int M, int N, int K, int lda)
{
    __shared__ __align__(16) float As[8][128];
    __shared__ __align__(16) float Ws[8][128];

    const int tid = threadIdx.x;
    const int tx  = tid & 15;         // 0..15  -> N
    const int ty  = tid >> 4;         // 0..15  -> M
    const int bm  = blockIdx.y * 128;
    const int bn  = blockIdx.x * 128;
    const int kper = K / gridDim.z;
    const int kbeg = blockIdx.z * kper;

    unsigned long long acc[4][8];
#pragma unroll
    for (int ip = 0; ip < 4; ip++)
#pragma unroll
        for (int j = 0; j < 8; j++) acc[ip][j] = 0ull;

    for (int k0 = kbeg; k0 < kbeg + kper; k0 += 8) {
        // ---- load A tile (128 x 8) ----
        if (ALAY == 0) {
            int row = tid >> 1;
            int kq  = (tid & 1) * 4;
            float4 v = *(const float4*)(A + (size_t)(bm + row) * lda + k0 + kq);
            As[kq + 0][row] = v.x; As[kq + 1][row] = v.y;
            As[kq + 2][row] = v.z; As[kq + 3][row] = v.w;
        } else {
#pragma unroll
            for (int j = 0; j < 4; j++) {
                int idx = tid + j * 256;
                int kk  = idx >> 7;
                int mm  = idx & 127;
                int m   = bm + mm;
                As[kk][mm] = A[((size_t)(m >> 11) * DMODEL + (k0 + kk)) * (size_t)LSEQ
                               + (m & (LSEQ - 1))];
            }
        }
        // ---- load W tile (128 x 8), zero-fill beyond N ----
        {
            int row = tid >> 1;
            int kq  = (tid & 1) * 4;
            int n   = bn + row;
            float4 v = make_float4(0.f, 0.f, 0.f, 0.f);
            if (n < N) v = *(const float4*)(W + (size_t)n * K + k0 + kq);
            Ws[kq + 0][row] = v.x; Ws[kq + 1][row] = v.y;
            Ws[kq + 2][row] = v.z; Ws[kq + 3][row] = v.w;
        }
        __syncthreads();

#pragma unroll
        for (int kk = 0; kk < 8; kk++) {
            const unsigned long long* Ap =
                (const unsigned long long*)&As[kk][ty * 8];
            unsigned long long a2[4];
            a2[0] = Ap[0]; a2[1] = Ap[1]; a2[2] = Ap[2]; a2[3] = Ap[3];
            float4 b0 = *(const float4*)&Ws[kk][tx * 4];
            float4 b1 = *(const float4*)&Ws[kk][64 + tx * 4];
            float rb[8] = {b0.x, b0.y, b0.z, b0.w, b1.x, b1.y, b1.z, b1.w};
#pragma unroll
            for (int j = 0; j < 8; j++) {
                unsigned rr = __float_as_uint(rb[j]);
                unsigned long long bd;
                asm("mov.b64 %0, {%1, %2};" : "=l"(bd) : "r"(rr), "r"(rr));
#pragma unroll
                for (int ip = 0; ip < 4; ip++)
                    asm("fma.rn.f32x2 %0, %1, %2, %0;"
                        : "+l"(acc[ip][j]) : "l"(a2[ip]), "l"(bd));
            }
        }
        __syncthreads();
    }

    // ---- epilogue ----
#pragma unroll
    for (int ip = 0; ip < 4; ip++) {
#pragma unroll
        for (int j = 0; j < 8; j++) {
            unsigned lo_u, hi_u;
            asm("mov.b64 {%0, %1}, %2;" : "=r"(lo_u), "=r"(hi_u) : "l"(acc[ip][j]));
            float v0 = __uint_as_float(lo_u);
            float v1 = __uint_as_float(hi_u);
            int m0 = bm + ty * 8 + 2 * ip;
            int n  = bn + ((j < 4) ? (tx * 4 + j) : (64 + tx * 4 + (j - 4)));
            if (n >= N) continue;
            if (EPI == 0) {
                size_t off = (size_t)blockIdx.z * (size_t)M * N;
                C[off + (size_t)m0 * N + n]       = v0;
                C[off + (size_t)(m0 + 1) * N + n] = v1;
            } else if (EPI == 1) {
                float b = bias[n];
                C[(size_t)m0 * N + n]       = softplusf(v0 + b);
                C[(size_t)(m0 + 1) * N + n] = softplusf(v1 + b);
            } else { // EPI == 2: transposed store to (B, DMODEL, L)
                float b = bias[n];
                int l0 = m0 & (LSEQ - 1);
                size_t base = ((size_t)(m0 >> 11) * DMODEL + n) * (size_t)LSEQ;
                C[base + l0]     = v0 + b;
                C[base + l0 + 1] = v1 + b;   // m0,m0+1 share batch (128 | 2048)
            }
        }
    }
}

// ---------------- depthwise causal conv (K=4) + SiLU ----------------
__global__ void conv_silu_k(const float* __restrict__ conv_w,
                            const float* __restrict__ conv_b)
{
    int idx = blockIdx.x * 256 + threadIdx.x;      // < BL * DINNER
    int m = idx >> 11;                              // row in (B*L)
    int e = idx & (DINNER - 1);
    int l = m & (LSEQ - 1);
    float acc = conv_b[e];
#pragma unroll
    for (int k = 0; k < 4; k++) {
        int ll = l + k - 3;
        if (ll >= 0)
            acc += conv_w[e * 4 + k] * g_xz[(size_t)(m + k - 3) * 4096 + e];
    }
    g_uc[(size_t)m * DINNER + e] = siluf(acc);
}

// ---------------- split-K reduction for x_proj ----------------
__global__ void reduce_xdbl_k()
{
    int i = blockIdx.x * 256 + threadIdx.x;        // < BL * 96
    float s = 0.f;
#pragma unroll
    for (int p = 0; p < 8; p++) s += g_part[(size_t)p * BL * XPN + i];
    g_xdbl[i] = s;
}

// ---------------- selective scan: 16 lanes per (b,d) channel ----------------
__global__ void scan_k(const float* __restrict__ A_log, const float* __restrict__ Dv)
{
    int g = blockIdx.x * 16 + (threadIdx.x >> 4);  // channel id, < 8192
    int n = threadIdx.x & 15;                      // state index
    int b = g >> 11;
    int d = g & (DINNER - 1);

    float Acoef = -__expf(A_log[d * DSTATE + n]);  // A = -exp(A_log)
    float Dd    = Dv[d];
    float h = 0.f;
    size_t rowbase = (size_t)b * LSEQ;

    for (int l = 0; l < LSEQ; l++) {
        size_t r = rowbase + l;
        float dval = g_delta[r * DINNER + d];
        float uval = g_uc  [r * DINNER + d];
        float Bv   = g_xdbl[r * XPN + DTRANK + n];
        float Cv   = g_xdbl[r * XPN + DTRANK + DSTATE + n];
        float dA = __expf(dval * Acoef);
        h = fmaf(dA, h, dval * Bv * uval);
        float p = h * Cv;
        p += __shfl_xor_sync(0xffffffffu, p, 1);
        p += __shfl_xor_sync(0xffffffffu, p, 2);
        p += __shfl_xor_sync(0xffffffffu, p, 4);
        p += __shfl_xor_sync(0xffffffffu, p, 8);
        if (n == 0) {
            float z  = g_xz[r * 4096 + DINNER + d];
            g_y[r * DINNER + d] = (p + uval * Dd) * siluf(z);
        }
    }
}

// ---------------- launch ----------------
extern "C" void kernel_launch(void* const* d_in, const int* in_sizes, int n_in,
                              void* d_out, int out_size)
{
    const float* x          = (const float*)d_in[0];
    const float* in_proj_w  = (const float*)d_in[1];
    const float* conv_w     = (const float*)d_in[2];
    const float* conv_b     = (const float*)d_in[3];
    const float* x_proj_w   = (const float*)d_in[4];
    const float* dt_proj_w  = (const float*)d_in[5];
    const float* dt_proj_b  = (const float*)d_in[6];
    const float* A_log      = (const float*)d_in[7];
    const float* Dv         = (const float*)d_in[8];
    const float* out_proj_w = (const float*)d_in[9];
    const float* proj_w     = (const float*)d_in[10];
    const float* proj_b     = (const float*)d_in[11];
    float* out = (float*)d_out;

    float *p_xz, *p_uc, *p_part, *p_xdbl, *p_delta, *p_y, *p_o1;
    cudaGetSymbolAddress((void**)&p_xz,    g_xz);
    cudaGetSymbolAddress((void**)&p_uc,    g_uc);
    cudaGetSymbolAddress((void**)&p_part,  g_part);
    cudaGetSymbolAddress((void**)&p_xdbl,  g_xdbl);
    cudaGetSymbolAddress((void**)&p_delta, g_delta);
    cudaGetSymbolAddress((void**)&p_y,     g_y);
    cudaGetSymbolAddress((void**)&p_o1,    g_o1);

    // 1) xz = x^T @ in_proj_w^T      (8192 x 4096, K=1024)
    gemm_k<1, 0><<<dim3(32, 64, 1), 256>>>(x, in_proj_w, nullptr, p_xz,
                                           BL, 4096, DMODEL, 0);
    // 2) depthwise conv + silu -> g_uc
    conv_silu_k<<<(BL * DINNER) / 256, 256>>>(conv_w, conv_b);
    // 3) x_dbl = u @ x_proj_w^T      (8192 x 96, K=2048), split-K=8
    gemm_k<0, 0><<<dim3(1, 64, 8), 256>>>(p_uc, x_proj_w, nullptr, p_part,
                                          BL, XPN, DINNER, DINNER);
    reduce_xdbl_k<<<(BL * XPN) / 256, 256>>>();
    // 4) delta = softplus(dt_low @ dt_proj_w^T + b)   (8192 x 2048, K=64, lda=96)
    gemm_k<0, 1><<<dim3(16, 64, 1), 256>>>(p_xdbl, dt_proj_w, dt_proj_b, p_delta,
                                           BL, DINNER, DTRANK, XPN);
    // 5) selective scan + gating -> g_y
    scan_k<<<512, 256>>>(A_log, Dv);
    // 6) o1 = y @ out_proj_w^T       (8192 x 1024, K=2048)
    gemm_k<0, 0><<<dim3(8, 64, 1), 256>>>(p_y, out_proj_w, nullptr, p_o1,
                                          BL, DMODEL, DINNER, DINNER);
    // 7) out = (o1 @ proj_w^T + b), stored transposed (B, DMODEL, L)
    gemm_k<0, 2><<<dim3(8, 64, 1), 256>>>(p_o1, proj_w, proj_b, out,
                                          BL, DMODEL, DMODEL, DMODEL);
}

// round 5
// speedup vs baseline: 1.2192x; 1.2192x over previous
#include <cuda_runtime.h>
#include <cuda_bf16.h>
#include <cstddef>
#include <cstdint>

// ---------------- problem constants ----------------
#define BQ     4
#define DMODEL 1024
#define LSEQ   2048
#define DINNER 2048
#define DSTATE 16
#define DTRANK 64
#define BL     8192          // BQ * LSEQ
#define XPN    96            // DTRANK + 2*DSTATE

// ---------------- scratch ----------------
__device__ float g_xT   [(size_t)BL * DMODEL];
__device__ float g_xz   [(size_t)BL * 4096];        // u | z
__device__ float g_uc   [(size_t)BL * DINNER];
__device__ float g_xdbl [(size_t)BL * XPN];
__device__ float g_delta[(size_t)BL * DINNER];
__device__ float g_y    [(size_t)BL * DINNER];
__device__ float g_o1   [(size_t)BL * DMODEL];

__device__ __forceinline__ float softplusf(float x) {
    return (x > 20.f) ? x : log1pf(__expf(x));
}
__device__ __forceinline__ float siluf(float x) {
    return x / (1.f + __expf(-x));
}

// split fp32 -> (bf16 hi, bf16 lo) pairs, packed two-k per u32
__device__ __forceinline__ void split_pair(float x0, float x1,
                                           uint32_t& h, uint32_t& l) {
    __nv_bfloat162 hh = __floats2bfloat162_rn(x0, x1);
    float f0 = __bfloat162float(hh.x);
    float f1 = __bfloat162float(hh.y);
    __nv_bfloat162 ll = __floats2bfloat162_rn(x0 - f0, x1 - f1);
    h = *reinterpret_cast<uint32_t*>(&hh);
    l = *reinterpret_cast<uint32_t*>(&ll);
}

#define MMA_BF16(d, a, b0v, b1v) \
    asm volatile("mma.sync.aligned.m16n8k16.row.col.f32.bf16.bf16.f32 " \
        "{%0,%1,%2,%3}, {%4,%5,%6,%7}, {%8,%9}, {%0,%1,%2,%3};" \
        : "+f"((d)[0]), "+f"((d)[1]), "+f"((d)[2]), "+f"((d)[3]) \
        : "r"((a)[0]), "r"((a)[1]), "r"((a)[2]), "r"((a)[3]), \
          "r"(b0v), "r"(b1v))

// ---------------- smem layout (bytes) ----------------
#define RSB      80            // row stride: 32 bf16 (64B) + 16B pad -> conflict-free
#define REG_ALO  10240
#define REG_BHI  20480
#define REG_BLO  30720
#define BUF_SZ   40960
#define TC_SMEM  (2 * BUF_SZ)  // 81920

// ---------------- x transpose: (B, DMODEL, L) -> (B*L, DMODEL) ----------------
__global__ void transpose_k(const float* __restrict__ x) {
    __shared__ float t[32][33];
    int b = blockIdx.z;
    int l0 = blockIdx.x * 32, k0 = blockIdx.y * 32;
    int tx = threadIdx.x, ty = threadIdx.y;
#pragma unroll
    for (int i = 0; i < 4; i++)
        t[ty + 8 * i][tx] = x[((size_t)(b * DMODEL + k0 + ty + 8 * i)) * LSEQ + l0 + tx];
    __syncthreads();
#pragma unroll
    for (int i = 0; i < 4; i++)
        g_xT[((size_t)(b * LSEQ + l0 + ty + 8 * i)) * DMODEL + k0 + tx] = t[tx][ty + 8 * i];
}

// ---------------- bf16x3 mma.sync GEMM: C[M,N] = A[M,K] @ W[N,K]^T ----------------
// EPI 0: plain store   1: softplus(acc + bias)   2: acc + bias, transposed store
template<int EPI>
__global__ void __launch_bounds__(256)
tc_gemm(const float* __restrict__ A, const float* __restrict__ W,
        const float* __restrict__ bias, float* __restrict__ C,
        int M, int N, int K, int lda, int ldc)
{
    extern __shared__ char smem[];
    const int tid  = threadIdx.x;
    const int wid  = tid >> 5, lane = tid & 31;
    const int lr   = lane >> 2, lc = lane & 3;
    const int wm   = wid >> 1, wn = wid & 1;
    const int bm   = blockIdx.y * 128, bn = blockIdx.x * 128;
    const int nc   = K >> 5;                       // K-chunks of 32

    // loader role: threads 0-127 -> A rows, 128-255 -> W rows
    const int half = tid >> 7;
    const int row  = tid & 127;
    const float* gp;
    bool valid;
    if (half == 0) { gp = A + (size_t)(bm + row) * lda; valid = true; }
    else { int n = bn + row; valid = (n < N); gp = W + (size_t)(valid ? n : 0) * K; }
    char* dst_base = smem + (half ? REG_BHI : 0) + row * RSB;

    float4 v[8];
    auto ldg = [&](int c) {
        const float* p = gp + (c << 5);
#pragma unroll
        for (int q = 0; q < 8; q++)
            v[q] = valid ? *((const float4*)p + q) : make_float4(0.f, 0.f, 0.f, 0.f);
    };
    auto sts = [&](int s) {
        char* hi = dst_base + s * BUF_SZ;
        char* lo = hi + REG_ALO;                   // +10240 for both A and B regions
#pragma unroll
        for (int f = 0; f < 4; f++) {
            uint32_t h0, l0v, h1, l1v, h2, l2v, h3, l3v;
            float4 va = v[2 * f], vb = v[2 * f + 1];
            split_pair(va.x, va.y, h0, l0v);
            split_pair(va.z, va.w, h1, l1v);
            split_pair(vb.x, vb.y, h2, l2v);
            split_pair(vb.z, vb.w, h3, l3v);
            *(uint4*)(hi + f * 16) = make_uint4(h0, h1, h2, h3);
            *(uint4*)(lo + f * 16) = make_uint4(l0v, l1v, l2v, l3v);
        }
    };

    float acc[2][8][4];
#pragma unroll
    for (int i = 0; i < 2; i++)
#pragma unroll
        for (int j = 0; j < 8; j++)
#pragma unroll
            for (int t = 0; t < 4; t++) acc[i][j][t] = 0.f;

    ldg(0); sts(0); __syncthreads();

    for (int c = 0; c < nc; c++) {
        const int s = c & 1;
        if (c + 1 < nc) ldg(c + 1);
        char* base = smem + s * BUF_SZ;
#pragma unroll
        for (int ks = 0; ks < 2; ks++) {           // two k16 steps per chunk
            uint32_t ah[2][4], al[2][4];
#pragma unroll
            for (int i = 0; i < 2; i++) {
                char* ar = base + (wm * 32 + i * 16 + lr) * RSB + ks * 32 + lc * 4;
                ah[i][0] = *(uint32_t*)ar;
                ah[i][1] = *(uint32_t*)(ar + 8 * RSB);
                ah[i][2] = *(uint32_t*)(ar + 16);
                ah[i][3] = *(uint32_t*)(ar + 8 * RSB + 16);
                char* alp = ar + REG_ALO;
                al[i][0] = *(uint32_t*)alp;
                al[i][1] = *(uint32_t*)(alp + 8 * RSB);
                al[i][2] = *(uint32_t*)(alp + 16);
                al[i][3] = *(uint32_t*)(alp + 8 * RSB + 16);
            }
#pragma unroll
            for (int j = 0; j < 8; j++) {
                char* br = base + REG_BHI + (wn * 64 + j * 8 + lr) * RSB + ks * 32 + lc * 4;
                uint32_t bh0 = *(uint32_t*)br;
                uint32_t bh1 = *(uint32_t*)(br + 16);
                uint32_t bl0 = *(uint32_t*)(br + 10240);
                uint32_t bl1 = *(uint32_t*)(br + 10240 + 16);
#pragma unroll
                for (int i = 0; i < 2; i++) {
                    MMA_BF16(acc[i][j], ah[i], bh0, bh1);
                    MMA_BF16(acc[i][j], ah[i], bl0, bl1);
                    MMA_BF16(acc[i][j], al[i], bh0, bh1);
                }
            }
        }
        if (c + 1 < nc) sts(s ^ 1);
        __syncthreads();
    }

    // ---------------- epilogue ----------------
#pragma unroll
    for (int i = 0; i < 2; i++) {
#pragma unroll
        for (int j = 0; j < 8; j++) {
            int r0 = bm + wm * 32 + i * 16 + lr;
            int cn = bn + wn * 64 + j * 8 + lc * 2;
            if (cn >= N) continue;
            float c0 = acc[i][j][0], c1 = acc[i][j][1];
            float c2 = acc[i][j][2], c3 = acc[i][j][3];
            if (EPI == 0) {
                *(float2*)&C[(size_t)r0 * ldc + cn]       = make_float2(c0, c1);
                *(float2*)&C[(size_t)(r0 + 8) * ldc + cn] = make_float2(c2, c3);
            } else if (EPI == 1) {
                float b0v = bias[cn], b1v = bias[cn + 1];
                *(float2*)&C[(size_t)r0 * ldc + cn] =
                    make_float2(softplusf(c0 + b0v), softplusf(c1 + b1v));
                *(float2*)&C[(size_t)(r0 + 8) * ldc + cn] =
                    make_float2(softplusf(c2 + b0v), softplusf(c3 + b1v));
            } else {
                float b0v = bias[cn], b1v = bias[cn + 1];
                int bb = r0 >> 11;
                int l0 = r0 & (LSEQ - 1);
                size_t base0 = ((size_t)(bb * DMODEL + cn)) * LSEQ;
                C[base0 + l0]            = c0 + b0v;
                C[base0 + LSEQ + l0]     = c1 + b1v;
                C[base0 + l0 + 8]        = c2 + b0v;   // r0+8: same batch, l+8
                C[base0 + LSEQ + l0 + 8] = c3 + b1v;
            }
        }
    }
}

// ---------------- depthwise causal conv (K=4) + SiLU ----------------
__global__ void conv_silu_k(const float* __restrict__ conv_w,
                            const float* __restrict__ conv_b)
{
    int idx = blockIdx.x * 256 + threadIdx.x;
    int m = idx >> 11;
    int e = idx & (DINNER - 1);
    int l = m & (LSEQ - 1);
    float acc = conv_b[e];
#pragma unroll
    for (int k = 0; k < 4; k++) {
        int ll = l + k - 3;
        if (ll >= 0)
            acc += conv_w[e * 4 + k] * g_xz[(size_t)(m + k - 3) * 4096 + e];
    }
    g_uc[(size_t)m * DINNER + e] = siluf(acc);
}

// ---------------- selective scan: 16 lanes per (b,d) channel ----------------
__global__ void scan_k(const float* __restrict__ A_log, const float* __restrict__ Dv)
{
    int g = blockIdx.x * 16 + (threadIdx.x >> 4);
    int n = threadIdx.x & 15;
    int b = g >> 11;
    int d = g & (DINNER - 1);

    float Acoef = -__expf(A_log[d * DSTATE + n]);
    float Dd    = Dv[d];
    float h = 0.f;
    size_t rowbase = (size_t)b * LSEQ;

    for (int l = 0; l < LSEQ; l++) {
        size_t r = rowbase + l;
        float dval = g_delta[r * DINNER + d];
        float uval = g_uc  [r * DINNER + d];
        float Bv   = g_xdbl[r * XPN + DTRANK + n];
        float Cv   = g_xdbl[r * XPN + DTRANK + DSTATE + n];
        float dA = __expf(dval * Acoef);
        h = fmaf(dA, h, dval * Bv * uval);
        float p = h * Cv;
        p += __shfl_xor_sync(0xffffffffu, p, 1);
        p += __shfl_xor_sync(0xffffffffu, p, 2);
        p += __shfl_xor_sync(0xffffffffu, p, 4);
        p += __shfl_xor_sync(0xffffffffu, p, 8);
        if (n == 0) {
            float z = g_xz[r * 4096 + DINNER + d];
            g_y[r * DINNER + d] = (p + uval * Dd) * siluf(z);
        }
    }
}

// ---------------- launch ----------------
extern "C" void kernel_launch(void* const* d_in, const int* in_sizes, int n_in,
                              void* d_out, int out_size)
{
    const float* x          = (const float*)d_in[0];
    const float* in_proj_w  = (const float*)d_in[1];
    const float* conv_w     = (const float*)d_in[2];
    const float* conv_b     = (const float*)d_in[3];
    const float* x_proj_w   = (const float*)d_in[4];
    const float* dt_proj_w  = (const float*)d_in[5];
    const float* dt_proj_b  = (const float*)d_in[6];
    const float* A_log      = (const float*)d_in[7];
    const float* Dv         = (const float*)d_in[8];
    const float* out_proj_w = (const float*)d_in[9];
    const float* proj_w     = (const float*)d_in[10];
    const float* proj_b     = (const float*)d_in[11];
    float* out = (float*)d_out;

    float *p_xT, *p_xz, *p_uc, *p_xdbl, *p_delta, *p_y, *p_o1;
    cudaGetSymbolAddress((void**)&p_xT,    g_xT);
    cudaGetSymbolAddress((void**)&p_xz,    g_xz);
    cudaGetSymbolAddress((void**)&p_uc,    g_uc);
    cudaGetSymbolAddress((void**)&p_xdbl,  g_xdbl);
    cudaGetSymbolAddress((void**)&p_delta, g_delta);
    cudaGetSymbolAddress((void**)&p_y,     g_y);
    cudaGetSymbolAddress((void**)&p_o1,    g_o1);

    cudaFuncSetAttribute(tc_gemm<0>, cudaFuncAttributeMaxDynamicSharedMemorySize, TC_SMEM);
    cudaFuncSetAttribute(tc_gemm<1>, cudaFuncAttributeMaxDynamicSharedMemorySize, TC_SMEM);
    cudaFuncSetAttribute(tc_gemm<2>, cudaFuncAttributeMaxDynamicSharedMemorySize, TC_SMEM);

    // 0) transpose x -> (B*L, DMODEL)
    transpose_k<<<dim3(LSEQ / 32, DMODEL / 32, BQ), dim3(32, 8)>>>(x);
    // 1) xz = xT @ in_proj_w^T          (8192 x 4096, K=1024)
    tc_gemm<0><<<dim3(32, 64), 256, TC_SMEM>>>(p_xT, in_proj_w, nullptr, p_xz,
                                               BL, 4096, DMODEL, DMODEL, 4096);
    // 2) depthwise conv + silu
    conv_silu_k<<<(BL * DINNER) / 256, 256>>>(conv_w, conv_b);
    // 3) x_dbl = u @ x_proj_w^T         (8192 x 96, K=2048)
    tc_gemm<0><<<dim3(1, 64), 256, TC_SMEM>>>(p_uc, x_proj_w, nullptr, p_xdbl,
                                              BL, XPN, DINNER, DINNER, XPN);
    // 4) delta = softplus(dt_low @ dt_proj_w^T + b)   (8192 x 2048, K=64)
    tc_gemm<1><<<dim3(16, 64), 256, TC_SMEM>>>(p_xdbl, dt_proj_w, dt_proj_b, p_delta,
                                               BL, DINNER, DTRANK, XPN, DINNER);
    // 5) selective scan + gating
    scan_k<<<512, 256>>>(A_log, Dv);
    // 6) o1 = y @ out_proj_w^T          (8192 x 1024, K=2048)
    tc_gemm<0><<<dim3(8, 64), 256, TC_SMEM>>>(p_y, out_proj_w, nullptr, p_o1,
                                              BL, DMODEL, DINNER, DINNER, DMODEL);
    // 7) out = (o1 @ proj_w^T + b), transposed store
    tc_gemm<2><<<dim3(8, 64), 256, TC_SMEM>>>(p_o1, proj_w, proj_b, out,
                                              BL, DMODEL, DMODEL, DMODEL, 0);
}